// round 5
// baseline (speedup 1.0000x reference)
#include <cuda_runtime.h>
#include <cuda_bf16.h>
#include <cstdint>

// Problem dims (fixed)
#define FDIM 1024
#define CDIM 128
#define BDIM 2048

#define BM 32
#define BN 64
#define BK 64
#define NITER (FDIM / BK)       // 16 stages, full K per CTA

// ---------------- scratch ----------------
__device__ __nv_bfloat16 g_bh[CDIM * FDIM];   // softmax(w) hi
__device__ __nv_bfloat16 g_bl[CDIM * FDIM];   // softmax(w) lo

// ---------------- helpers ----------------
__device__ __forceinline__ uint32_t smem_u32(const void* p) {
    uint32_t a;
    asm("{ .reg .u64 t; cvta.to.shared.u64 t, %1; cvt.u32.u64 %0, t; }" : "=r"(a) : "l"(p));
    return a;
}
__device__ __forceinline__ uint32_t swz(uint32_t row, uint32_t colByte) {
    return row * 128u + (colByte ^ ((row & 7u) << 4));
}
#define CP_ASYNC16(sm, g) asm volatile("cp.async.cg.shared.global [%0], [%1], 16;" :: "r"(sm), "l"(g) : "memory")
#define CP_COMMIT()       asm volatile("cp.async.commit_group;" ::: "memory")
#define CP_WAIT1()        asm volatile("cp.async.wait_group 1;" ::: "memory")
#define CP_WAIT0()        asm volatile("cp.async.wait_group 0;" ::: "memory")

#define LDMATRIX_X4(r0, r1, r2, r3, addr)                                     \
    asm volatile("ldmatrix.sync.aligned.m8n8.x4.shared.b16 {%0,%1,%2,%3}, [%4];" \
                 : "=r"(r0), "=r"(r1), "=r"(r2), "=r"(r3) : "r"(addr))

#define MMA_BF16(d, a, b)                                                     \
    asm volatile("mma.sync.aligned.m16n8k16.row.col.f32.bf16.bf16.f32 "       \
                 "{%0,%1,%2,%3}, {%4,%5,%6,%7}, {%8,%9}, {%0,%1,%2,%3};"      \
                 : "+f"((d)[0]), "+f"((d)[1]), "+f"((d)[2]), "+f"((d)[3])     \
                 : "r"((a)[0]), "r"((a)[1]), "r"((a)[2]), "r"((a)[3]),        \
                   "r"((b)[0]), "r"((b)[1]))

__device__ __forceinline__ void split_bf16(float v, __nv_bfloat16& h, __nv_bfloat16& l) {
    h = __float2bfloat16(v);
    l = __float2bfloat16(v - __bfloat162float(h));
}

// ---------------------------------------------------------------------------
// Kernel 1: softmax(weight) rows -> Bh/Bl  [C, F] K-major
// ---------------------------------------------------------------------------
__global__ void __launch_bounds__(256) prep_w_kernel(const float* __restrict__ w) {
    const int c = blockIdx.x;
    const float* row = w + c * FDIM;
    __shared__ float red[256];
    const int t = threadIdx.x;

    float m = -1e30f;
    for (int f = t; f < FDIM; f += 256) m = fmaxf(m, row[f]);
    red[t] = m;
    __syncthreads();
    for (int s = 128; s > 0; s >>= 1) { if (t < s) red[t] = fmaxf(red[t], red[t + s]); __syncthreads(); }
    m = red[0];
    __syncthreads();

    float sum = 0.0f;
    for (int f = t; f < FDIM; f += 256) sum += __expf(row[f] - m);
    red[t] = sum;
    __syncthreads();
    for (int s = 128; s > 0; s >>= 1) { if (t < s) red[t] += red[t + s]; __syncthreads(); }
    const float inv = 1.0f / red[0];

    for (int f = t; f < FDIM; f += 256) {
        float p = __expf(row[f] - m) * inv;
        __nv_bfloat16 h, l;
        split_bf16(p, h, l);
        g_bh[c * FDIM + f] = h;
        g_bl[c * FDIM + f] = l;
    }
}

// ---------------------------------------------------------------------------
// Kernel 2: fused exp->split->HMMA->log. 128 CTAs x 256 threads (8 warps).
// Warp grid 2(M) x 4(N); warp tile 16x16. 3-stage smem pipeline:
// iter it: MMA(stage it) || convert A(stage it+2) || cp.async B(stage it+2)
//          || LDG x(stage it+3).
// 3 independent accumulator sets (hh/lh/hl) for MMA ILP.
// ---------------------------------------------------------------------------
#define OFF_AH 0
#define OFF_AL 4096
#define OFF_BH 8192
#define OFF_BL 16384
#define STAGE_BYTES 24576
#define NSTAGE 3
#define SMEM_TOTAL (NSTAGE * STAGE_BYTES)   // 73728

__device__ __forceinline__ void load_x(float4* xv, const float* __restrict__ xbase,
                                       int kOff, int tid) {
#pragma unroll
    for (int t = 0; t < 2; t++) {
        const int idx = tid + t * 256;              // 0..511
        const uint32_t row = (uint32_t)idx >> 4;    // 0..31
        const uint32_t c4  = (uint32_t)idx & 15;    // float4 within 64-col stage
        xv[t] = *reinterpret_cast<const float4*>(xbase + (size_t)row * FDIM + kOff + c4 * 4);
    }
}

__device__ __forceinline__ void convert_x(char* stage, const float4* xv, int tid) {
#pragma unroll
    for (int t = 0; t < 2; t++) {
        const int idx = tid + t * 256;
        const uint32_t row = (uint32_t)idx >> 4;
        const uint32_t c4  = (uint32_t)idx & 15;
        float4 v = xv[t];
        float e0 = __expf(v.x), e1 = __expf(v.y), e2 = __expf(v.z), e3 = __expf(v.w);
        __nv_bfloat16 h0, l0, h1, l1, h2, l2, h3, l3;
        split_bf16(e0, h0, l0); split_bf16(e1, h1, l1);
        split_bf16(e2, h2, l2); split_bf16(e3, h3, l3);
        ushort4 hv = make_ushort4(__bfloat16_as_ushort(h0), __bfloat16_as_ushort(h1),
                                  __bfloat16_as_ushort(h2), __bfloat16_as_ushort(h3));
        ushort4 lv = make_ushort4(__bfloat16_as_ushort(l0), __bfloat16_as_ushort(l1),
                                  __bfloat16_as_ushort(l2), __bfloat16_as_ushort(l3));
        const uint32_t byteOff = swz(row, (c4 >> 1) * 16) + (c4 & 1) * 8;
        *reinterpret_cast<ushort4*>(stage + OFF_AH + byteOff) = hv;
        *reinterpret_cast<ushort4*>(stage + OFF_AL + byteOff) = lv;
    }
}

__device__ __forceinline__ void issue_b(uint32_t stageBase, int nsplit, int kOff, int tid) {
#pragma unroll
    for (int t = 0; t < 2; t++) {
        const int idx = tid + t * 256;              // 0..511
        const uint32_t row = (uint32_t)idx >> 3;    // 0..63
        const uint32_t c   = (uint32_t)idx & 7;     // 16B chunk
        const size_t src = (size_t)(nsplit * BN + row) * FDIM + kOff + c * 8;
        CP_ASYNC16(stageBase + OFF_BH + swz(row, c * 16), g_bh + src);
        CP_ASYNC16(stageBase + OFF_BL + swz(row, c * 16), g_bl + src);
    }
    CP_COMMIT();
}

__global__ void __launch_bounds__(256) mma_kernel(const float* __restrict__ x,
                                                  float* __restrict__ out) {
    extern __shared__ char smem[];
    const uint32_t sbase = smem_u32(smem);
    const int tid  = threadIdx.x;
    const int warp = tid >> 5;
    const int lane = tid & 31;
    const int wm   = warp >> 2;    // 0..1, M half
    const int wn   = warp & 3;     // 0..3, N quarter

    const int mtile  = (int)blockIdx.x >> 1;
    const int nsplit = (int)blockIdx.x & 1;

    float accA[2][4], accB[2][4], accC[2][4];   // hh, lh, hl passes
#pragma unroll
    for (int j = 0; j < 2; j++)
#pragma unroll
        for (int e = 0; e < 4; e++) { accA[j][e] = 0.0f; accB[j][e] = 0.0f; accC[j][e] = 0.0f; }

    const uint32_t aRow = (lane & 7) + ((lane >> 3) & 1) * 8;
    const uint32_t aCol = (lane >> 4) * 16;
    const uint32_t bRow = ((lane >> 4) & 1) * 8 + (lane & 7);
    const uint32_t bCol = ((lane >> 3) & 1) * 16;

    const float* xbase = x + (size_t)mtile * BM * FDIM;

    float4 xv[2], xnv[2];

    // Prologue: fill stages 0,1; preload x for stage 2
    load_x(xv, xbase, 0, tid);
    convert_x(smem + 0 * STAGE_BYTES, xv, tid);
    issue_b(sbase + 0 * STAGE_BYTES, nsplit, 0, tid);
    load_x(xv, xbase, BK, tid);
    convert_x(smem + 1 * STAGE_BYTES, xv, tid);
    issue_b(sbase + 1 * STAGE_BYTES, nsplit, BK, tid);
    load_x(xv, xbase, 2 * BK, tid);
    CP_WAIT1();
    __syncthreads();

    for (int it = 0; it < NITER; it++) {
        const int s = it % 3;
        const uint32_t cur = sbase + (uint32_t)s * STAGE_BYTES;
        const bool issue = (it + 2 < NITER);

        if (issue) {
            if (it + 3 < NITER) load_x(xnv, xbase, (it + 3) * BK, tid);
            const int s2 = (it + 2) % 3;
            convert_x(smem + s2 * STAGE_BYTES, xv, tid);
            issue_b(sbase + (uint32_t)s2 * STAGE_BYTES, nsplit, (it + 2) * BK, tid);
        }

#pragma unroll
        for (int kstep = 0; kstep < BK / 16; kstep++) {
            const uint32_t kb = kstep * 32;
            uint32_t ah[4], al[4];
            {
                const uint32_t row = wm * 16 + aRow;
                LDMATRIX_X4(ah[0], ah[1], ah[2], ah[3], cur + OFF_AH + swz(row, kb + aCol));
                LDMATRIX_X4(al[0], al[1], al[2], al[3], cur + OFF_AL + swz(row, kb + aCol));
            }
            uint32_t bh[2][2], bl[2][2];
            {
                const uint32_t row = wn * 16 + bRow;
                uint32_t r0, r1, r2, r3;
                LDMATRIX_X4(r0, r1, r2, r3, cur + OFF_BH + swz(row, kb + bCol));
                bh[0][0] = r0; bh[0][1] = r1; bh[1][0] = r2; bh[1][1] = r3;
                LDMATRIX_X4(r0, r1, r2, r3, cur + OFF_BL + swz(row, kb + bCol));
                bl[0][0] = r0; bl[0][1] = r1; bl[1][0] = r2; bl[1][1] = r3;
            }
#pragma unroll
            for (int ni = 0; ni < 2; ni++) {
                MMA_BF16(accA[ni], ah, bh[ni]);
                MMA_BF16(accB[ni], al, bh[ni]);
                MMA_BF16(accC[ni], ah, bl[ni]);
            }
        }

        if (issue) { CP_WAIT1(); } else { CP_WAIT0(); }
        __syncthreads();

        if (it + 3 < NITER) { xv[0] = xnv[0]; xv[1] = xnv[1]; }
    }

    // Epilogue: sum passes, log, direct store
#pragma unroll
    for (int ni = 0; ni < 2; ni++) {
        float s0 = accA[ni][0] + accB[ni][0] + accC[ni][0];
        float s1 = accA[ni][1] + accB[ni][1] + accC[ni][1];
        float s2 = accA[ni][2] + accB[ni][2] + accC[ni][2];
        float s3 = accA[ni][3] + accB[ni][3] + accC[ni][3];
        const int m = mtile * BM + wm * 16 + (lane >> 2);
        const int n = nsplit * BN + wn * 16 + ni * 8 + (lane & 3) * 2;
        *reinterpret_cast<float2*>(out + (size_t)m * CDIM + n) =
            make_float2(__logf(s0), __logf(s1));
        *reinterpret_cast<float2*>(out + (size_t)(m + 8) * CDIM + n) =
            make_float2(__logf(s2), __logf(s3));
    }
}

// ---------------------------------------------------------------------------
extern "C" void kernel_launch(void* const* d_in, const int* in_sizes, int n_in,
                              void* d_out, int out_size) {
    const float* x = (const float*)d_in[0];
    const float* w = (const float*)d_in[1];
    if (n_in >= 2 && in_sizes[0] == CDIM * FDIM && in_sizes[1] == BDIM * FDIM) {
        w = (const float*)d_in[0];
        x = (const float*)d_in[1];
    }
    float* out = (float*)d_out;

    static bool attr_set = false;
    if (!attr_set) {
        cudaFuncSetAttribute(mma_kernel, cudaFuncAttributeMaxDynamicSharedMemorySize, SMEM_TOTAL);
        attr_set = true;
    }

    prep_w_kernel<<<CDIM, 256>>>(w);
    mma_kernel<<<(BDIM / BM) * (CDIM / BN), 256, SMEM_TOTAL>>>(x, out);
}

// round 6
// speedup vs baseline: 1.3831x; 1.3831x over previous
#include <cuda_runtime.h>
#include <cuda_fp16.h>
#include <cstdint>

// Problem dims (fixed)
#define FDIM 1024
#define CDIM 128
#define BDIM 2048

#define BM 16
#define BN 64
#define BK 128
#define NITER (FDIM / BK)       // 8
#define NSTAGE 3

// ---------------- scratch ----------------
__device__ __half g_b[CDIM * FDIM];   // softmax(w) fp16, [c][k] k-major

// ---------------- helpers ----------------
__device__ __forceinline__ uint32_t smem_u32(const void* p) {
    uint32_t a;
    asm("{ .reg .u64 t; cvta.to.shared.u64 t, %1; cvt.u32.u64 %0, t; }" : "=r"(a) : "l"(p));
    return a;
}
// 256B-row tile, 16B-granularity XOR swizzle (LDSM/STS conflict-free)
__device__ __forceinline__ uint32_t swz256(uint32_t row, uint32_t colByte) {
    return row * 256u + (colByte ^ ((row & 7u) << 4));
}
#define CP_ASYNC16(sm, g) asm volatile("cp.async.cg.shared.global [%0], [%1], 16;" :: "r"(sm), "l"(g) : "memory")
#define CP_COMMIT()       asm volatile("cp.async.commit_group;" ::: "memory")
#define CP_WAIT1()        asm volatile("cp.async.wait_group 1;" ::: "memory")
#define CP_WAIT0()        asm volatile("cp.async.wait_group 0;" ::: "memory")

#define LDMATRIX_X4(r0, r1, r2, r3, addr)                                        \
    asm volatile("ldmatrix.sync.aligned.m8n8.x4.shared.b16 {%0,%1,%2,%3}, [%4];" \
                 : "=r"(r0), "=r"(r1), "=r"(r2), "=r"(r3) : "r"(addr))
#define LDMATRIX_X2(r0, r1, addr)                                                \
    asm volatile("ldmatrix.sync.aligned.m8n8.x2.shared.b16 {%0,%1}, [%2];"       \
                 : "=r"(r0), "=r"(r1) : "r"(addr))

#define MMA_F16(d, a, b)                                                         \
    asm volatile("mma.sync.aligned.m16n8k16.row.col.f32.f16.f16.f32 "            \
                 "{%0,%1,%2,%3}, {%4,%5,%6,%7}, {%8,%9}, {%0,%1,%2,%3};"         \
                 : "+f"((d)[0]), "+f"((d)[1]), "+f"((d)[2]), "+f"((d)[3])        \
                 : "r"((a)[0]), "r"((a)[1]), "r"((a)[2]), "r"((a)[3]),           \
                   "r"((b)[0]), "r"((b)[1]))

// ---------------------------------------------------------------------------
// Kernel 1: softmax(weight) rows -> g_b fp16  [C, F] k-major
// ---------------------------------------------------------------------------
__global__ void __launch_bounds__(256) prep_w_kernel(const float* __restrict__ w) {
    const int c = blockIdx.x;
    const float* row = w + c * FDIM;
    __shared__ float red[256];
    const int t = threadIdx.x;

    float m = -1e30f;
    for (int f = t; f < FDIM; f += 256) m = fmaxf(m, row[f]);
    red[t] = m;
    __syncthreads();
    for (int s = 128; s > 0; s >>= 1) { if (t < s) red[t] = fmaxf(red[t], red[t + s]); __syncthreads(); }
    m = red[0];
    __syncthreads();

    float sum = 0.0f;
    for (int f = t; f < FDIM; f += 256) sum += __expf(row[f] - m);
    red[t] = sum;
    __syncthreads();
    for (int s = 128; s > 0; s >>= 1) { if (t < s) red[t] += red[t + s]; __syncthreads(); }
    const float inv = 1.0f / red[0];

    for (int f = t; f < FDIM; f += 256)
        g_b[c * FDIM + f] = __float2half_rn(__expf(row[f] - m) * inv);
}

// ---------------------------------------------------------------------------
// Kernel 2: fused exp->fp16 HMMA GEMM->log. 256 CTAs (128 M x 2 N), 256 thr.
// Warp tile 16x8 (8 warps cover BN=64). BK=128, 3-stage pipeline:
// it: MMA(stage it) after [load x(it+3) | convert A(it+2) | cp.async B(it+2)].
// ---------------------------------------------------------------------------
#define OFF_A 0
#define OFF_B 4096
#define STAGE_BYTES 20480          // A 16x256B + B 64x256B
#define SMEM_TOTAL (NSTAGE * STAGE_BYTES)   // 61440

__device__ __forceinline__ void load_x(float4* xv, const float* __restrict__ xbase,
                                       int kOff, int tid) {
#pragma unroll
    for (int t = 0; t < 2; t++) {
        const int idx = tid + t * 256;              // 0..511
        const uint32_t row = (uint32_t)idx >> 5;    // 0..15
        const uint32_t c4  = (uint32_t)idx & 31;    // float4 within 128-col row
        xv[t] = *reinterpret_cast<const float4*>(xbase + (size_t)row * FDIM + kOff + c4 * 4);
    }
}

__device__ __forceinline__ void convert_x(char* stage, const float4* xv, int tid) {
#pragma unroll
    for (int t = 0; t < 2; t++) {
        const int idx = tid + t * 256;
        const uint32_t row = (uint32_t)idx >> 5;
        const uint32_t c4  = (uint32_t)idx & 31;
        float4 v = xv[t];
        __half2 h01 = __floats2half2_rn(__expf(v.x), __expf(v.y));
        __half2 h23 = __floats2half2_rn(__expf(v.z), __expf(v.w));
        uint2 pv = make_uint2(*reinterpret_cast<uint32_t*>(&h01),
                              *reinterpret_cast<uint32_t*>(&h23));
        *reinterpret_cast<uint2*>(stage + OFF_A + swz256(row, c4 * 8)) = pv;
    }
}

__device__ __forceinline__ void issue_b(uint32_t stageBase, int nsplit, int kOff, int tid) {
#pragma unroll
    for (int t = 0; t < 4; t++) {
        const int idx = tid + t * 256;              // 0..1023
        const uint32_t row = (uint32_t)idx >> 4;    // 0..63
        const uint32_t c16 = (uint32_t)idx & 15;    // 16B chunk (8 fp16)
        const __half* src = g_b + (size_t)(nsplit * BN + row) * FDIM + kOff + c16 * 8;
        CP_ASYNC16(stageBase + OFF_B + swz256(row, c16 * 16), src);
    }
    CP_COMMIT();
}

__global__ void __launch_bounds__(256) mma_kernel(const float* __restrict__ x,
                                                  float* __restrict__ out) {
    extern __shared__ char smem[];
    const uint32_t sbase = smem_u32(smem);
    const int tid  = threadIdx.x;
    const int warp = tid >> 5;     // 0..7 -> n8 tile
    const int lane = tid & 31;

    const int mtile  = (int)blockIdx.x >> 1;   // 0..127
    const int nsplit = (int)blockIdx.x & 1;

    float acc0[4], acc1[4];        // k-parity split accumulator chains
#pragma unroll
    for (int e = 0; e < 4; e++) { acc0[e] = 0.0f; acc1[e] = 0.0f; }

    // ldmatrix lane address components
    const uint32_t aRow = (lane & 7) + ((lane >> 3) & 1) * 8;   // 0..15
    const uint32_t aCol = (lane >> 4) * 16;
    const uint32_t bRow = warp * 8 + (lane & 7);                // n row
    const uint32_t bCol = ((lane >> 3) & 1) * 16;               // lanes 0..15 used

    const float* xbase = x + (size_t)mtile * BM * FDIM;

    float4 xv[2], xnv[2];

    // Prologue: stages 0 and 1 filled; x for stage 2 preloaded
    load_x(xv, xbase, 0, tid);
    convert_x(smem + 0 * STAGE_BYTES, xv, tid);
    issue_b(sbase + 0 * STAGE_BYTES, nsplit, 0, tid);
    load_x(xv, xbase, BK, tid);
    convert_x(smem + 1 * STAGE_BYTES, xv, tid);
    issue_b(sbase + 1 * STAGE_BYTES, nsplit, BK, tid);
    load_x(xv, xbase, 2 * BK, tid);
    CP_WAIT1();
    __syncthreads();

#pragma unroll
    for (int it = 0; it < NITER; it++) {
        const uint32_t cur = sbase + (uint32_t)(it % 3) * STAGE_BYTES;
        const bool issue = (it + 2 < NITER);

        if (issue) {
            if (it + 3 < NITER) load_x(xnv, xbase, (it + 3) * BK, tid);
            const int s2 = (it + 2) % 3;
            convert_x(smem + s2 * STAGE_BYTES, xv, tid);
            issue_b(sbase + (uint32_t)s2 * STAGE_BYTES, nsplit, (it + 2) * BK, tid);
        }

#pragma unroll
        for (int kstep = 0; kstep < BK / 16; kstep++) {
            const uint32_t kb = kstep * 32;
            uint32_t a[4], b[2];
            LDMATRIX_X4(a[0], a[1], a[2], a[3], cur + OFF_A + swz256(aRow, kb + aCol));
            LDMATRIX_X2(b[0], b[1],             cur + OFF_B + swz256(bRow, kb + bCol));
            if (kstep & 1) { MMA_F16(acc1, a, b); } else { MMA_F16(acc0, a, b); }
        }

        if (it + 1 < NITER) {
            if (issue) { CP_WAIT1(); } else { CP_WAIT0(); }
            __syncthreads();
        }
        if (it + 3 < NITER) { xv[0] = xnv[0]; xv[1] = xnv[1]; }
    }

    // Epilogue: sum chains, log, direct store
    const float s0 = acc0[0] + acc1[0];
    const float s1 = acc0[1] + acc1[1];
    const float s2 = acc0[2] + acc1[2];
    const float s3 = acc0[3] + acc1[3];
    const int m = mtile * BM + (lane >> 2);
    const int n = nsplit * BN + warp * 8 + (lane & 3) * 2;
    *reinterpret_cast<float2*>(out + (size_t)m * CDIM + n) =
        make_float2(__logf(s0), __logf(s1));
    *reinterpret_cast<float2*>(out + (size_t)(m + 8) * CDIM + n) =
        make_float2(__logf(s2), __logf(s3));
}

// ---------------------------------------------------------------------------
extern "C" void kernel_launch(void* const* d_in, const int* in_sizes, int n_in,
                              void* d_out, int out_size) {
    const float* x = (const float*)d_in[0];
    const float* w = (const float*)d_in[1];
    if (n_in >= 2 && in_sizes[0] == CDIM * FDIM && in_sizes[1] == BDIM * FDIM) {
        w = (const float*)d_in[0];
        x = (const float*)d_in[1];
    }
    float* out = (float*)d_out;

    static bool attr_set = false;
    if (!attr_set) {
        cudaFuncSetAttribute(mma_kernel, cudaFuncAttributeMaxDynamicSharedMemorySize, SMEM_TOTAL);
        attr_set = true;
    }

    prep_w_kernel<<<CDIM, 256>>>(w);
    mma_kernel<<<(BDIM / BM) * (CDIM / BN), 256, SMEM_TOTAL>>>(x, out);
}

// round 7
// speedup vs baseline: 1.5923x; 1.1513x over previous
#include <cuda_runtime.h>
#include <cuda_fp16.h>
#include <cstdint>

// Problem dims (fixed)
#define FDIM 1024
#define CDIM 128
#define BDIM 2048

#define BM 16
#define BN 128
#define BK 128
#define NITER (FDIM / BK)       // 8
#define NSTAGE 3

// ---------------- scratch ----------------
__device__ __half g_b[CDIM * FDIM];   // softmax(w) fp16, [c][k] k-major

// ---------------- helpers ----------------
__device__ __forceinline__ uint32_t smem_u32(const void* p) {
    uint32_t a;
    asm("{ .reg .u64 t; cvta.to.shared.u64 t, %1; cvt.u32.u64 %0, t; }" : "=r"(a) : "l"(p));
    return a;
}
// 256B-row tile, 16B-granularity XOR swizzle
__device__ __forceinline__ uint32_t swz256(uint32_t row, uint32_t colByte) {
    return row * 256u + (colByte ^ ((row & 7u) << 4));
}
#define CP_ASYNC16(sm, g) asm volatile("cp.async.cg.shared.global [%0], [%1], 16;" :: "r"(sm), "l"(g) : "memory")
#define CP_COMMIT()       asm volatile("cp.async.commit_group;" ::: "memory")
#define CP_WAIT1()        asm volatile("cp.async.wait_group 1;" ::: "memory")
#define CP_WAIT0()        asm volatile("cp.async.wait_group 0;" ::: "memory")

#define LDMATRIX_X4(r0, r1, r2, r3, addr)                                        \
    asm volatile("ldmatrix.sync.aligned.m8n8.x4.shared.b16 {%0,%1,%2,%3}, [%4];" \
                 : "=r"(r0), "=r"(r1), "=r"(r2), "=r"(r3) : "r"(addr))

#define MMA_F16(d, a, b)                                                         \
    asm volatile("mma.sync.aligned.m16n8k16.row.col.f32.f16.f16.f32 "            \
                 "{%0,%1,%2,%3}, {%4,%5,%6,%7}, {%8,%9}, {%0,%1,%2,%3};"         \
                 : "+f"((d)[0]), "+f"((d)[1]), "+f"((d)[2]), "+f"((d)[3])        \
                 : "r"((a)[0]), "r"((a)[1]), "r"((a)[2]), "r"((a)[3]),           \
                   "r"((b)[0]), "r"((b)[1]))

// ---------------------------------------------------------------------------
// Kernel 1: warp-per-class softmax(weight) -> g_b fp16. 128 warps, shfl-only.
// Lane holds 32 elements (8 strided float4), no smem, no syncthreads.
// ---------------------------------------------------------------------------
__global__ void __launch_bounds__(256) prep_w_kernel(const float* __restrict__ w) {
    const int gw   = (blockIdx.x * 256 + threadIdx.x) >> 5;   // 0..127 class
    const int lane = threadIdx.x & 31;
    const float* row = w + (size_t)gw * FDIM;

    float4 v[8];
    float m = -1e30f;
#pragma unroll
    for (int j = 0; j < 8; j++) {
        v[j] = *reinterpret_cast<const float4*>(row + j * 128 + lane * 4);
        m = fmaxf(m, fmaxf(fmaxf(v[j].x, v[j].y), fmaxf(v[j].z, v[j].w)));
    }
#pragma unroll
    for (int s = 16; s > 0; s >>= 1) m = fmaxf(m, __shfl_xor_sync(0xffffffffu, m, s));

    float sum = 0.0f;
#pragma unroll
    for (int j = 0; j < 8; j++) {
        v[j].x = __expf(v[j].x - m); v[j].y = __expf(v[j].y - m);
        v[j].z = __expf(v[j].z - m); v[j].w = __expf(v[j].w - m);
        sum += (v[j].x + v[j].y) + (v[j].z + v[j].w);
    }
#pragma unroll
    for (int s = 16; s > 0; s >>= 1) sum += __shfl_xor_sync(0xffffffffu, sum, s);
    const float inv = 1.0f / sum;

#pragma unroll
    for (int j = 0; j < 8; j++) {
        __half2 h01 = __floats2half2_rn(v[j].x * inv, v[j].y * inv);
        __half2 h23 = __floats2half2_rn(v[j].z * inv, v[j].w * inv);
        uint2 pv = make_uint2(*reinterpret_cast<uint32_t*>(&h01),
                              *reinterpret_cast<uint32_t*>(&h23));
        *reinterpret_cast<uint2*>(g_b + (size_t)gw * FDIM + j * 128 + lane * 4) = pv;
    }
}

// ---------------------------------------------------------------------------
// Kernel 2: fused exp->fp16 HMMA GEMM->log. 128 CTAs (one per M tile of 16),
// 256 threads, 8 warps covering BN=128 (warp tile 16x16). BK=128, 3 stages.
// it: MMA(stage it) after [LDG x(it+3) | convert A(it+2) | cp.async B(it+2)].
// ---------------------------------------------------------------------------
#define OFF_A 0
#define OFF_B 4096
#define STAGE_BYTES 36864          // A 16x256B (4KB) + B 128x256B (32KB)
#define SMEM_TOTAL (NSTAGE * STAGE_BYTES)   // 110592

__device__ __forceinline__ void load_x(float4* xv, const float* __restrict__ xbase,
                                       int kOff, int tid) {
#pragma unroll
    for (int t = 0; t < 2; t++) {
        const int idx = tid + t * 256;              // 0..511
        const uint32_t row = (uint32_t)idx >> 5;    // 0..15
        const uint32_t c4  = (uint32_t)idx & 31;    // float4 within 128-col row
        xv[t] = *reinterpret_cast<const float4*>(xbase + (size_t)row * FDIM + kOff + c4 * 4);
    }
}

__device__ __forceinline__ void convert_x(char* stage, const float4* xv, int tid) {
#pragma unroll
    for (int t = 0; t < 2; t++) {
        const int idx = tid + t * 256;
        const uint32_t row = (uint32_t)idx >> 5;
        const uint32_t c4  = (uint32_t)idx & 31;
        float4 v = xv[t];
        __half2 h01 = __floats2half2_rn(__expf(v.x), __expf(v.y));
        __half2 h23 = __floats2half2_rn(__expf(v.z), __expf(v.w));
        uint2 pv = make_uint2(*reinterpret_cast<uint32_t*>(&h01),
                              *reinterpret_cast<uint32_t*>(&h23));
        const uint32_t byteOff = swz256(row, (c4 >> 1) * 16) + (c4 & 1) * 8;
        *reinterpret_cast<uint2*>(stage + OFF_A + byteOff) = pv;
    }
}

__device__ __forceinline__ void issue_b(uint32_t stageBase, int kOff, int tid) {
#pragma unroll
    for (int t = 0; t < 8; t++) {
        const int idx = tid + t * 256;              // 0..2047
        const uint32_t row = (uint32_t)idx >> 4;    // 0..127
        const uint32_t c16 = (uint32_t)idx & 15;    // 16B chunk (8 fp16)
        const __half* src = g_b + (size_t)row * FDIM + kOff + c16 * 8;
        CP_ASYNC16(stageBase + OFF_B + swz256(row, c16 * 16), src);
    }
    CP_COMMIT();
}

__global__ void __launch_bounds__(256) mma_kernel(const float* __restrict__ x,
                                                  float* __restrict__ out) {
    extern __shared__ char smem[];
    const uint32_t sbase = smem_u32(smem);
    const int tid  = threadIdx.x;
    const int warp = tid >> 5;     // n range [warp*16, warp*16+16)
    const int lane = tid & 31;

    const int mtile = (int)blockIdx.x;   // 0..127

    float acc[2][2][4];            // [k-parity][ni]
#pragma unroll
    for (int p = 0; p < 2; p++)
#pragma unroll
        for (int j = 0; j < 2; j++)
#pragma unroll
            for (int e = 0; e < 4; e++) acc[p][j][e] = 0.0f;

    // ldmatrix lane address components
    const uint32_t aRow = (lane & 7) + ((lane >> 3) & 1) * 8;
    const uint32_t aCol = (lane >> 4) * 16;
    const uint32_t bRow = warp * 16 + ((lane >> 4) & 1) * 8 + (lane & 7);
    const uint32_t bCol = ((lane >> 3) & 1) * 16;

    const float* xbase = x + (size_t)mtile * BM * FDIM;

    float4 xv[2], xnv[2];

    // Prologue: stages 0,1 filled; x for stage 2 preloaded
    load_x(xv, xbase, 0, tid);
    convert_x(smem + 0 * STAGE_BYTES, xv, tid);
    issue_b(sbase + 0 * STAGE_BYTES, 0, tid);
    load_x(xv, xbase, BK, tid);
    convert_x(smem + 1 * STAGE_BYTES, xv, tid);
    issue_b(sbase + 1 * STAGE_BYTES, BK, tid);
    load_x(xv, xbase, 2 * BK, tid);
    CP_WAIT1();
    __syncthreads();

#pragma unroll
    for (int it = 0; it < NITER; it++) {
        const uint32_t cur = sbase + (uint32_t)(it % 3) * STAGE_BYTES;
        const bool issue = (it + 2 < NITER);

        if (issue) {
            if (it + 3 < NITER) load_x(xnv, xbase, (it + 3) * BK, tid);
            const int s2 = (it + 2) % 3;
            convert_x(smem + s2 * STAGE_BYTES, xv, tid);
            issue_b(sbase + (uint32_t)s2 * STAGE_BYTES, (it + 2) * BK, tid);
        }

#pragma unroll
        for (int kstep = 0; kstep < BK / 16; kstep++) {
            const uint32_t kb = kstep * 32;
            uint32_t a[4], b[4];
            LDMATRIX_X4(a[0], a[1], a[2], a[3], cur + OFF_A + swz256(aRow, kb + aCol));
            LDMATRIX_X4(b[0], b[1], b[2], b[3], cur + OFF_B + swz256(bRow, kb + bCol));
            const int p = kstep & 1;
            MMA_F16(acc[p][0], a, b);        // b[0],b[1] = first n8
            MMA_F16(acc[p][1], a, b + 2);    // b[2],b[3] = second n8
        }

        if (it + 1 < NITER) {
            if (issue) { CP_WAIT1(); } else { CP_WAIT0(); }
            __syncthreads();
        }
        if (it + 3 < NITER) { xv[0] = xnv[0]; xv[1] = xnv[1]; }
    }

    // Epilogue: sum k-parity chains, log, store
#pragma unroll
    for (int ni = 0; ni < 2; ni++) {
        const float s0 = acc[0][ni][0] + acc[1][ni][0];
        const float s1 = acc[0][ni][1] + acc[1][ni][1];
        const float s2 = acc[0][ni][2] + acc[1][ni][2];
        const float s3 = acc[0][ni][3] + acc[1][ni][3];
        const int m = mtile * BM + (lane >> 2);
        const int n = warp * 16 + ni * 8 + (lane & 3) * 2;
        *reinterpret_cast<float2*>(out + (size_t)m * CDIM + n) =
            make_float2(__logf(s0), __logf(s1));
        *reinterpret_cast<float2*>(out + (size_t)(m + 8) * CDIM + n) =
            make_float2(__logf(s2), __logf(s3));
    }
}

// ---------------------------------------------------------------------------
extern "C" void kernel_launch(void* const* d_in, const int* in_sizes, int n_in,
                              void* d_out, int out_size) {
    const float* x = (const float*)d_in[0];
    const float* w = (const float*)d_in[1];
    if (n_in >= 2 && in_sizes[0] == CDIM * FDIM && in_sizes[1] == BDIM * FDIM) {
        w = (const float*)d_in[0];
        x = (const float*)d_in[1];
    }
    float* out = (float*)d_out;

    static bool attr_set = false;
    if (!attr_set) {
        cudaFuncSetAttribute(mma_kernel, cudaFuncAttributeMaxDynamicSharedMemorySize, SMEM_TOTAL);
        attr_set = true;
    }

    prep_w_kernel<<<CDIM / 8, 256>>>(w);
    mma_kernel<<<BDIM / BM, 256, SMEM_TOTAL>>>(x, out);
}

// round 8
// speedup vs baseline: 1.6130x; 1.0130x over previous
#include <cuda_runtime.h>
#include <cuda_fp16.h>
#include <cstdint>

// Problem dims (fixed)
#define FDIM 1024
#define CDIM 128
#define BDIM 2048

#define BM 16
#define BN 128
#define BK 128
#define NITER (FDIM / BK)       // 8
#define NSTAGE 3
#define THREADS 512

// ---------------- scratch ----------------
__device__ __half g_b[CDIM * FDIM];   // softmax(w) fp16, [c][k] k-major

// ---------------- helpers ----------------
__device__ __forceinline__ uint32_t smem_u32(const void* p) {
    uint32_t a;
    asm("{ .reg .u64 t; cvta.to.shared.u64 t, %1; cvt.u32.u64 %0, t; }" : "=r"(a) : "l"(p));
    return a;
}
// 256B-row tile, 16B-granularity XOR swizzle
__device__ __forceinline__ uint32_t swz256(uint32_t row, uint32_t colByte) {
    return row * 256u + (colByte ^ ((row & 7u) << 4));
}
#define CP_ASYNC16(sm, g) asm volatile("cp.async.cg.shared.global [%0], [%1], 16;" :: "r"(sm), "l"(g) : "memory")
#define CP_COMMIT()       asm volatile("cp.async.commit_group;" ::: "memory")
#define CP_WAIT1()        asm volatile("cp.async.wait_group 1;" ::: "memory")
#define CP_WAIT0()        asm volatile("cp.async.wait_group 0;" ::: "memory")

#define LDMATRIX_X4(r0, r1, r2, r3, addr)                                        \
    asm volatile("ldmatrix.sync.aligned.m8n8.x4.shared.b16 {%0,%1,%2,%3}, [%4];" \
                 : "=r"(r0), "=r"(r1), "=r"(r2), "=r"(r3) : "r"(addr))
#define LDMATRIX_X2(r0, r1, addr)                                                \
    asm volatile("ldmatrix.sync.aligned.m8n8.x2.shared.b16 {%0,%1}, [%2];"       \
                 : "=r"(r0), "=r"(r1) : "r"(addr))

#define MMA_F16(d, a, b)                                                         \
    asm volatile("mma.sync.aligned.m16n8k16.row.col.f32.f16.f16.f32 "            \
                 "{%0,%1,%2,%3}, {%4,%5,%6,%7}, {%8,%9}, {%0,%1,%2,%3};"         \
                 : "+f"((d)[0]), "+f"((d)[1]), "+f"((d)[2]), "+f"((d)[3])        \
                 : "r"((a)[0]), "r"((a)[1]), "r"((a)[2]), "r"((a)[3]),           \
                   "r"((b)[0]), "r"((b)[1]))

// ---------------------------------------------------------------------------
// Kernel 1: warp-per-class softmax(weight) -> g_b fp16 (shfl-only)
// ---------------------------------------------------------------------------
__global__ void __launch_bounds__(256) prep_w_kernel(const float* __restrict__ w) {
    const int gw   = (blockIdx.x * 256 + threadIdx.x) >> 5;   // class 0..127
    const int lane = threadIdx.x & 31;
    const float* row = w + (size_t)gw * FDIM;

    float4 v[8];
    float m = -1e30f;
#pragma unroll
    for (int j = 0; j < 8; j++) {
        v[j] = *reinterpret_cast<const float4*>(row + j * 128 + lane * 4);
        m = fmaxf(m, fmaxf(fmaxf(v[j].x, v[j].y), fmaxf(v[j].z, v[j].w)));
    }
#pragma unroll
    for (int s = 16; s > 0; s >>= 1) m = fmaxf(m, __shfl_xor_sync(0xffffffffu, m, s));

    float sum = 0.0f;
#pragma unroll
    for (int j = 0; j < 8; j++) {
        v[j].x = __expf(v[j].x - m); v[j].y = __expf(v[j].y - m);
        v[j].z = __expf(v[j].z - m); v[j].w = __expf(v[j].w - m);
        sum += (v[j].x + v[j].y) + (v[j].z + v[j].w);
    }
#pragma unroll
    for (int s = 16; s > 0; s >>= 1) sum += __shfl_xor_sync(0xffffffffu, sum, s);
    const float inv = 1.0f / sum;

#pragma unroll
    for (int j = 0; j < 8; j++) {
        __half2 h01 = __floats2half2_rn(v[j].x * inv, v[j].y * inv);
        __half2 h23 = __floats2half2_rn(v[j].z * inv, v[j].w * inv);
        uint2 pv = make_uint2(*reinterpret_cast<uint32_t*>(&h01),
                              *reinterpret_cast<uint32_t*>(&h23));
        *reinterpret_cast<uint2*>(g_b + (size_t)gw * FDIM + j * 128 + lane * 4) = pv;
    }
}

// ---------------------------------------------------------------------------
// Kernel 2: fused exp->fp16 HMMA GEMM->log. 128 CTAs x 512 threads (16 warps).
// Warp tile 16x8 (16 warps cover BN=128). BK=128, 3-stage pipeline.
// ---------------------------------------------------------------------------
#define OFF_A 0
#define OFF_B 4096
#define STAGE_BYTES 36864          // A 16x256B (4KB) + B 128x256B (32KB)
#define SMEM_TOTAL (NSTAGE * STAGE_BYTES)   // 110592

__device__ __forceinline__ void load_x(float4& xv, const float* __restrict__ xbase,
                                       int kOff, int tid) {
    const uint32_t row = (uint32_t)tid >> 5;    // 0..15
    const uint32_t c4  = (uint32_t)tid & 31;    // float4 within 128-col row
    xv = *reinterpret_cast<const float4*>(xbase + (size_t)row * FDIM + kOff + c4 * 4);
}

__device__ __forceinline__ void convert_x(char* stage, const float4 xv, int tid) {
    const uint32_t row = (uint32_t)tid >> 5;
    const uint32_t c4  = (uint32_t)tid & 31;
    __half2 h01 = __floats2half2_rn(__expf(xv.x), __expf(xv.y));
    __half2 h23 = __floats2half2_rn(__expf(xv.z), __expf(xv.w));
    uint2 pv = make_uint2(*reinterpret_cast<uint32_t*>(&h01),
                          *reinterpret_cast<uint32_t*>(&h23));
    const uint32_t byteOff = swz256(row, (c4 >> 1) * 16) + (c4 & 1) * 8;
    *reinterpret_cast<uint2*>(stage + OFF_A + byteOff) = pv;
}

__device__ __forceinline__ void issue_b(uint32_t stageBase, int kOff, int tid) {
#pragma unroll
    for (int t = 0; t < 4; t++) {
        const int idx = tid + t * THREADS;          // 0..2047
        const uint32_t row = (uint32_t)idx >> 4;    // 0..127
        const uint32_t c16 = (uint32_t)idx & 15;    // 16B chunk (8 fp16)
        const __half* src = g_b + (size_t)row * FDIM + kOff + c16 * 8;
        CP_ASYNC16(stageBase + OFF_B + swz256(row, c16 * 16), src);
    }
    CP_COMMIT();
}

__global__ void __launch_bounds__(THREADS) mma_kernel(const float* __restrict__ x,
                                                      float* __restrict__ out) {
    extern __shared__ char smem[];
    const uint32_t sbase = smem_u32(smem);
    const int tid  = threadIdx.x;
    const int warp = tid >> 5;     // 0..15 -> n8 tile
    const int lane = tid & 31;

    const int mtile = (int)blockIdx.x;   // 0..127

    float acc0[4], acc1[4];        // k-parity accumulator chains
#pragma unroll
    for (int e = 0; e < 4; e++) { acc0[e] = 0.0f; acc1[e] = 0.0f; }

    // ldmatrix lane address components
    const uint32_t aRow = (lane & 7) + ((lane >> 3) & 1) * 8;   // 0..15
    const uint32_t aCol = (lane >> 4) * 16;
    const uint32_t bRow = warp * 8 + (lane & 7);
    const uint32_t bCol = ((lane >> 3) & 1) * 16;               // lanes 0..15 used

    const float* xbase = x + (size_t)mtile * BM * FDIM;

    float4 xv, xnv;

    // Prologue: stages 0,1 filled; x for stage 2 preloaded
    load_x(xv, xbase, 0, tid);
    convert_x(smem + 0 * STAGE_BYTES, xv, tid);
    issue_b(sbase + 0 * STAGE_BYTES, 0, tid);
    load_x(xv, xbase, BK, tid);
    convert_x(smem + 1 * STAGE_BYTES, xv, tid);
    issue_b(sbase + 1 * STAGE_BYTES, BK, tid);
    load_x(xv, xbase, 2 * BK, tid);
    CP_WAIT1();
    __syncthreads();

#pragma unroll
    for (int it = 0; it < NITER; it++) {
        const uint32_t cur = sbase + (uint32_t)(it % 3) * STAGE_BYTES;
        const bool issue = (it + 2 < NITER);

        if (issue) {
            if (it + 3 < NITER) load_x(xnv, xbase, (it + 3) * BK, tid);
            const int s2 = (it + 2) % 3;
            convert_x(smem + s2 * STAGE_BYTES, xv, tid);
            issue_b(sbase + (uint32_t)s2 * STAGE_BYTES, (it + 2) * BK, tid);
        }

#pragma unroll
        for (int kstep = 0; kstep < BK / 16; kstep++) {
            const uint32_t kb = kstep * 32;
            uint32_t a[4], b[2];
            LDMATRIX_X4(a[0], a[1], a[2], a[3], cur + OFF_A + swz256(aRow, kb + aCol));
            LDMATRIX_X2(b[0], b[1],             cur + OFF_B + swz256(bRow, kb + bCol));
            if (kstep & 1) { MMA_F16(acc1, a, b); } else { MMA_F16(acc0, a, b); }
        }

        if (it + 1 < NITER) {
            if (issue) { CP_WAIT1(); } else { CP_WAIT0(); }
            __syncthreads();
        }
        if (it + 3 < NITER) xv = xnv;
    }

    // Epilogue: sum chains, log, direct store
    const float s0 = acc0[0] + acc1[0];
    const float s1 = acc0[1] + acc1[1];
    const float s2 = acc0[2] + acc1[2];
    const float s3 = acc0[3] + acc1[3];
    const int m = mtile * BM + (lane >> 2);
    const int n = warp * 8 + (lane & 3) * 2;
    *reinterpret_cast<float2*>(out + (size_t)m * CDIM + n) =
        make_float2(__logf(s0), __logf(s1));
    *reinterpret_cast<float2*>(out + (size_t)(m + 8) * CDIM + n) =
        make_float2(__logf(s2), __logf(s3));
}

// ---------------------------------------------------------------------------
extern "C" void kernel_launch(void* const* d_in, const int* in_sizes, int n_in,
                              void* d_out, int out_size) {
    const float* x = (const float*)d_in[0];
    const float* w = (const float*)d_in[1];
    if (n_in >= 2 && in_sizes[0] == CDIM * FDIM && in_sizes[1] == BDIM * FDIM) {
        w = (const float*)d_in[0];
        x = (const float*)d_in[1];
    }
    float* out = (float*)d_out;

    static bool attr_set = false;
    if (!attr_set) {
        cudaFuncSetAttribute(mma_kernel, cudaFuncAttributeMaxDynamicSharedMemorySize, SMEM_TOTAL);
        attr_set = true;
    }

    prep_w_kernel<<<CDIM / 8, 256>>>(w);
    mma_kernel<<<BDIM / BM, THREADS, SMEM_TOTAL>>>(x, out);
}